// round 3
// baseline (speedup 1.0000x reference)
#include <cuda_runtime.h>
#include <math.h>

#define SEQ    4096
#define DIM    1024
#define HEADS  16
#define DHEAD  64

// Scratch (allocation-free rule: __device__ globals)
__device__ float g_Q[SEQ * DIM];
__device__ float g_K[SEQ * DIM];
__device__ float g_V[SEQ * DIM];
__device__ float g_O[SEQ * DIM];

// ---------------------------------------------------------------------------
// Tiled fp32 GEMM: C[M,N] = A[M,K] @ B[K,N] (+ bias). All row-major.
// BM=BN=128, BK=16, 256 threads, 8x8 micro-tile per thread.
// M,N,K must be multiples of the tile sizes (true here: 4096/1024/1024).
// ---------------------------------------------------------------------------
template <bool BIAS>
__global__ void __launch_bounds__(256)
gemm_kernel(const float* __restrict__ A, const float* __restrict__ B,
            const float* __restrict__ bias, float* __restrict__ C,
            int M, int N, int K)
{
    __shared__ float As[16][128];   // transposed A tile: As[k][row]
    __shared__ float Bs[16][128];   // Bs[k][col]

    const int tid = threadIdx.x;
    const int tx = tid & 15;        // 0..15 -> col group
    const int ty = tid >> 4;        // 0..15 -> row group
    const int row0 = blockIdx.y * 128;
    const int col0 = blockIdx.x * 128;

    float acc[8][8];
#pragma unroll
    for (int i = 0; i < 8; i++)
#pragma unroll
        for (int j = 0; j < 8; j++) acc[i][j] = 0.f;

    for (int k0 = 0; k0 < K; k0 += 16) {
        // Load A tile (128x16) transposed into As
#pragma unroll
        for (int i = 0; i < 2; i++) {
            int aIdx = tid * 2 + i;            // 0..511
            int r  = aIdx >> 2;                // 0..127
            int c4 = aIdx & 3;                 // 0..3
            float4 a = *(const float4*)&A[(size_t)(row0 + r) * K + k0 + c4 * 4];
            As[c4 * 4 + 0][r] = a.x;
            As[c4 * 4 + 1][r] = a.y;
            As[c4 * 4 + 2][r] = a.z;
            As[c4 * 4 + 3][r] = a.w;
        }
        // Load B tile (16x128)
#pragma unroll
        for (int i = 0; i < 2; i++) {
            int bIdx = tid * 2 + i;            // 0..511
            int r  = bIdx >> 5;                // 0..15
            int c4 = bIdx & 31;                // 0..31
            *(float4*)&Bs[r][c4 * 4] =
                *(const float4*)&B[(size_t)(k0 + r) * N + col0 + c4 * 4];
        }
        __syncthreads();

#pragma unroll
        for (int k = 0; k < 16; k++) {
            float a[8], b[8];
            *(float4*)&a[0] = *(float4*)&As[k][ty * 8];
            *(float4*)&a[4] = *(float4*)&As[k][ty * 8 + 4];
            *(float4*)&b[0] = *(float4*)&Bs[k][tx * 8];
            *(float4*)&b[4] = *(float4*)&Bs[k][tx * 8 + 4];
#pragma unroll
            for (int i = 0; i < 8; i++)
#pragma unroll
                for (int j = 0; j < 8; j++)
                    acc[i][j] += a[i] * b[j];
        }
        __syncthreads();
    }

#pragma unroll
    for (int i = 0; i < 8; i++) {
        int r = row0 + ty * 8 + i;
#pragma unroll
        for (int j = 0; j < 8; j += 4) {
            int c = col0 + tx * 8 + j;
            float4 v = *(float4*)&acc[i][j];
            if (BIAS) {
                v.x += bias[c + 0];
                v.y += bias[c + 1];
                v.z += bias[c + 2];
                v.w += bias[c + 3];
            }
            *(float4*)&C[(size_t)r * N + c] = v;
        }
    }
}

// ---------------------------------------------------------------------------
// Causal flash attention, fp32.
// Grid: (SEQ/128, HEADS). Block: 128 threads, one query row per thread.
// Q row (scaled) and O accumulator live in registers; K/V 64x64 tiles in smem
// (broadcast reads); per-row score vector staged in padded smem (stride 65 ->
// conflict-free).
// Dynamic smem: Ks 64*64 + Vs 64*64 + Ss 128*65 floats = 66048 B.
// ---------------------------------------------------------------------------
#define ATTN_SMEM ((64 * 64 + 64 * 64 + 128 * 65) * 4)

__global__ void __launch_bounds__(128)
attn_kernel(const float* __restrict__ Qg, const float* __restrict__ Kg,
            const float* __restrict__ Vg, float* __restrict__ Og)
{
    extern __shared__ float smem[];
    float* Ks = smem;                 // [64][64]
    float* Vs = smem + 64 * 64;       // [64][64]
    float* Ss = smem + 2 * 64 * 64;   // [128][65]

    const int h  = blockIdx.y;
    const int qb = blockIdx.x;
    const int r  = threadIdx.x;       // 0..127
    const int qg = qb * 128 + r;      // global query row
    const float beta = 0.125f;        // 1/sqrt(64)

    float4 q[16], o[16];
    const float* qptr = Qg + (size_t)qg * DIM + h * DHEAD;
#pragma unroll
    for (int i = 0; i < 16; i++) {
        float4 t = *(const float4*)&qptr[i * 4];
        t.x *= beta; t.y *= beta; t.z *= beta; t.w *= beta;
        q[i] = t;
        o[i] = make_float4(0.f, 0.f, 0.f, 0.f);
    }

    float m = -1e30f, l = 0.f;
    float* Srow = Ss + r * 65;

    const int nkb = qb * 2 + 2;       // key blocks of 64 covering causal range
    for (int kb = 0; kb < nkb; kb++) {
        const int j0 = kb * 64;

        __syncthreads();              // protect K/V tiles from previous iter
        // Cooperative load of K,V tiles (64x64 each): 1024 float4s / 128 thr
#pragma unroll
        for (int i = 0; i < 8; i++) {
            int f4  = threadIdx.x + i * 128;  // 0..1023
            int row = f4 >> 4;                // 0..63
            int c4  = f4 & 15;                // 0..15
            *(float4*)&Ks[row * 64 + c4 * 4] =
                *(const float4*)&Kg[(size_t)(j0 + row) * DIM + h * DHEAD + c4 * 4];
            *(float4*)&Vs[row * 64 + c4 * 4] =
                *(const float4*)&Vg[(size_t)(j0 + row) * DIM + h * DHEAD + c4 * 4];
        }
        __syncthreads();

        if (qg >= j0) {               // otherwise entire block is masked: no-op
            const bool full = (j0 + 63 <= qg);
            float mb = -1e30f;
            // Pass 1: scores for 64 keys, track block max
#pragma unroll 4
            for (int j = 0; j < 64; j++) {
                float s;
                if (full || (j0 + j) <= qg) {
                    float a0 = 0.f, a1 = 0.f, a2 = 0.f, a3 = 0.f;
                    const float* kr = Ks + j * 64;
#pragma unroll
                    for (int i = 0; i < 16; i++) {
                        float4 kk = *(const float4*)&kr[i * 4];
                        a0 += q[i].x * kk.x;
                        a1 += q[i].y * kk.y;
                        a2 += q[i].z * kk.z;
                        a3 += q[i].w * kk.w;
                    }
                    s = (a0 + a1) + (a2 + a3);
                } else {
                    s = -1e30f;
                }
                Srow[j] = s;
                mb = fmaxf(mb, s);
            }

            // Online softmax rescale
            const float mnew = fmaxf(m, mb);
            const float csc = __expf(m - mnew);
            m = mnew;
            l *= csc;
#pragma unroll
            for (int i = 0; i < 16; i++) {
                o[i].x *= csc; o[i].y *= csc; o[i].z *= csc; o[i].w *= csc;
            }

            // Pass 2: p = exp(s - m), accumulate O += p * V
#pragma unroll 2
            for (int j = 0; j < 64; j++) {
                float p = __expf(Srow[j] - mnew);
                l += p;
                const float* vr = Vs + j * 64;
#pragma unroll
                for (int i = 0; i < 16; i++) {
                    float4 vv = *(const float4*)&vr[i * 4];
                    o[i].x += p * vv.x;
                    o[i].y += p * vv.y;
                    o[i].z += p * vv.z;
                    o[i].w += p * vv.w;
                }
            }
        }
    }

    const float inv = 1.f / l;
    float* optr = Og + (size_t)qg * DIM + h * DHEAD;
#pragma unroll
    for (int i = 0; i < 16; i++) {
        float4 t = o[i];
        t.x *= inv; t.y *= inv; t.z *= inv; t.w *= inv;
        *(float4*)&optr[i * 4] = t;
    }
}

// ---------------------------------------------------------------------------
// Launch: x@Wq, x@Wk, x@Wv -> flash attention -> O@Wo + bo
// Inputs (metadata order): x, Wq, Wk, Wv, Wo, bo
// ---------------------------------------------------------------------------
extern "C" void kernel_launch(void* const* d_in, const int* in_sizes, int n_in,
                              void* d_out, int out_size)
{
    const float* x  = (const float*)d_in[0];
    const float* Wq = (const float*)d_in[1];
    const float* Wk = (const float*)d_in[2];
    const float* Wv = (const float*)d_in[3];
    const float* Wo = (const float*)d_in[4];
    const float* bo = (const float*)d_in[5];
    float* out = (float*)d_out;

    float *Qb, *Kb, *Vb, *Ob;
    cudaGetSymbolAddress((void**)&Qb, g_Q);
    cudaGetSymbolAddress((void**)&Kb, g_K);
    cudaGetSymbolAddress((void**)&Vb, g_V);
    cudaGetSymbolAddress((void**)&Ob, g_O);

    cudaFuncSetAttribute(attn_kernel,
                         cudaFuncAttributeMaxDynamicSharedMemorySize, ATTN_SMEM);

    dim3 ggrid(DIM / 128, SEQ / 128);   // (8, 32)
    gemm_kernel<false><<<ggrid, 256>>>(x, Wq, nullptr, Qb, SEQ, DIM, DIM);
    gemm_kernel<false><<<ggrid, 256>>>(x, Wk, nullptr, Kb, SEQ, DIM, DIM);
    gemm_kernel<false><<<ggrid, 256>>>(x, Wv, nullptr, Vb, SEQ, DIM, DIM);

    dim3 agrid(SEQ / 128, HEADS);       // (32, 16)
    attn_kernel<<<agrid, 128, ATTN_SMEM>>>(Qb, Kb, Vb, Ob);

    gemm_kernel<true><<<ggrid, 256>>>(Ob, Wo, bo, out, SEQ, DIM, DIM);
}

// round 6
// speedup vs baseline: 1.2121x; 1.2121x over previous
#include <cuda_runtime.h>
#include <cuda_bf16.h>
#include <math.h>
#include <stdint.h>

#define SEQ    4096
#define DIM    1024
#define HEADS  16
#define DHEAD  64
#define KP     (3 * DIM)          // split-K': [hi|hi|lo] / [hi|lo|hi]
#define BK     32                 // K-chunk per iter (bf16 elems, 64B)
#define NIT    (KP / BK)          // 96

// ---------------- scratch (__device__ globals; no allocs allowed) ----------
__device__ float g_Q[SEQ * DIM];
__device__ float g_K[SEQ * DIM];
__device__ float g_V[SEQ * DIM];
__device__ float g_O[SEQ * DIM];
__device__ __nv_bfloat16 g_XS[SEQ * KP];        // split x
__device__ __nv_bfloat16 g_WTq[DIM * KP];       // split+transposed weights
__device__ __nv_bfloat16 g_WTk[DIM * KP];
__device__ __nv_bfloat16 g_WTv[DIM * KP];
__device__ __nv_bfloat16 g_WTo[DIM * KP];
__device__ __nv_bfloat16 g_OS[SEQ * KP];        // split attention output

// ---------------- helpers (all non-arch-specific PTX: sm_80+) --------------
__device__ __forceinline__ uint32_t smem_u32(const void* p) {
    return (uint32_t)__cvta_generic_to_shared(p);
}
__device__ __forceinline__ void cp16(uint32_t dst, const void* src) {
    asm volatile("cp.async.cg.shared.global [%0], [%1], 16;"
                 :: "r"(dst), "l"(src) : "memory");
}
__device__ __forceinline__ void cp_commit() {
    asm volatile("cp.async.commit_group;" ::: "memory");
}
template <int N>
__device__ __forceinline__ void cp_wait() {
    asm volatile("cp.async.wait_group %0;" :: "n"(N) : "memory");
}
__device__ __forceinline__ void ldm_x4(uint32_t* r, uint32_t addr) {
    asm volatile("ldmatrix.sync.aligned.m8n8.x4.shared.b16 {%0,%1,%2,%3}, [%4];"
                 : "=r"(r[0]), "=r"(r[1]), "=r"(r[2]), "=r"(r[3]) : "r"(addr));
}
__device__ __forceinline__ void mma16816(float* c, const uint32_t* a,
                                         const uint32_t* b) {
    asm volatile("mma.sync.aligned.m16n8k16.row.col.f32.bf16.bf16.f32 "
                 "{%0,%1,%2,%3}, {%4,%5,%6,%7}, {%8,%9}, {%0,%1,%2,%3};"
                 : "+f"(c[0]), "+f"(c[1]), "+f"(c[2]), "+f"(c[3])
                 : "r"(a[0]), "r"(a[1]), "r"(a[2]), "r"(a[3]),
                   "r"(b[0]), "r"(b[1]));
}

// ---------------------------------------------------------------------------
// Split conversions for fp32 emulation via bf16 (unchanged from R5 design):
// A-side row-major: XS[m, 0..K)=hi, [K..2K)=hi, [2K..3K)=lo
// B-side transposed: WT[n, 0..K)=hi, [K..2K)=lo, [2K..3K)=hi
// ---------------------------------------------------------------------------
__global__ void __launch_bounds__(256)
split_a_kernel(const float* __restrict__ X, __nv_bfloat16* __restrict__ XS, int K)
{
    int idx = (blockIdx.x * 256 + threadIdx.x) * 4;
    int m = idx / K, k = idx % K;
    float4 v = *(const float4*)(X + idx);
    __nv_bfloat16 h0 = __float2bfloat16(v.x), h1 = __float2bfloat16(v.y);
    __nv_bfloat16 h2 = __float2bfloat16(v.z), h3 = __float2bfloat16(v.w);
    __nv_bfloat16 l0 = __float2bfloat16(v.x - __bfloat162float(h0));
    __nv_bfloat16 l1 = __float2bfloat16(v.y - __bfloat162float(h1));
    __nv_bfloat16 l2 = __float2bfloat16(v.z - __bfloat162float(h2));
    __nv_bfloat16 l3 = __float2bfloat16(v.w - __bfloat162float(h3));
    __nv_bfloat162 hA = __nv_bfloat162(h0, h1), hB = __nv_bfloat162(h2, h3);
    __nv_bfloat162 lA = __nv_bfloat162(l0, l1), lB = __nv_bfloat162(l2, l3);
    __nv_bfloat162* base = (__nv_bfloat162*)(XS + (size_t)m * (3 * K) + k);
    base[0] = hA; base[1] = hB;
    base[K / 2] = hA; base[K / 2 + 1] = hB;
    base[K] = lA; base[K + 1] = lB;
}

__global__ void __launch_bounds__(256)
split_w_kernel(const float* __restrict__ W, __nv_bfloat16* __restrict__ WT, int K, int N)
{
    __shared__ float t[32][33];
    const int tx = threadIdx.x & 31, ty = threadIdx.x >> 5;  // (32, 8)
    const int k0 = blockIdx.y * 32, n0 = blockIdx.x * 32;
#pragma unroll
    for (int i = 0; i < 4; i++)
        t[ty + i * 8][tx] = W[(size_t)(k0 + ty + i * 8) * N + n0 + tx];
    __syncthreads();
#pragma unroll
    for (int i = 0; i < 4; i++) {
        float v = t[tx][ty + i * 8];
        __nv_bfloat16 h = __float2bfloat16(v);
        __nv_bfloat16 l = __float2bfloat16(v - __bfloat162float(h));
        int n = n0 + ty + i * 8;
        __nv_bfloat16* row = WT + (size_t)n * (3 * K);
        row[k0 + tx] = h;
        row[K + k0 + tx] = l;
        row[2 * K + k0 + tx] = h;
    }
}

// ---------------------------------------------------------------------------
// HMMA GEMM (TN): C[M,N] = A'[M,KP] @ Bt'[N,KP]^T, bf16 in, fp32 accum.
// CTA 128x128, 256 thr (2x4 warps, warp tile 64x32), BK=32, cp.async double
// buffer. SMEM rows padded to 80B -> conflict-free ldmatrix.
// ---------------------------------------------------------------------------
#define ROWB   80                          // padded row stride (bytes)
#define TILEB  (128 * ROWB)                // 10240 B per tile

template <bool BIAS>
__global__ void __launch_bounds__(256, 2)
gemm_mma_kernel(const __nv_bfloat16* __restrict__ A,
                const __nv_bfloat16* __restrict__ Bt,
                const float* __restrict__ bias, float* __restrict__ C, int N)
{
    __shared__ __align__(128) char smem[4 * TILEB];  // A0,A1,B0,B1

    const int tid  = threadIdx.x;
    const int lane = tid & 31, wid = tid >> 5;
    const int wm0  = (wid & 1) * 64;        // warp M offset in CTA tile
    const int wn0  = (wid >> 1) * 32;       // warp N offset
    const int m0 = blockIdx.y * 128, n0 = blockIdx.x * 128;

    const uint32_t sbase = smem_u32(smem);
    const uint32_t sA[2] = { sbase,             sbase + TILEB };
    const uint32_t sB[2] = { sbase + 2 * TILEB, sbase + 3 * TILEB };

    float acc[4][4][4];
#pragma unroll
    for (int i = 0; i < 4; i++)
#pragma unroll
        for (int j = 0; j < 4; j++)
#pragma unroll
            for (int r = 0; r < 4; r++) acc[i][j][r] = 0.f;

    // G2S loader: 512 16B chunks per tile, 2 per thread per tile
    const int lrow = tid >> 2, lc16 = tid & 3;   // chunk = tid: row 0..63
    auto load_tile = [&](int c, int b) {
        const int kc0 = c * BK;
#pragma unroll
        for (int i = 0; i < 2; i++) {
            int row = lrow + i * 64;
            uint32_t so = (uint32_t)(row * ROWB + lc16 * 16);
            cp16(sA[b] + so, A  + (size_t)(m0 + row) * KP + kc0 + lc16 * 8);
            cp16(sB[b] + so, Bt + (size_t)(n0 + row) * KP + kc0 + lc16 * 8);
        }
        cp_commit();
    };

    load_tile(0, 0);

    for (int c = 0; c < NIT; c++) {
        const int b = c & 1;
        if (c + 1 < NIT) { load_tile(c + 1, b ^ 1); cp_wait<1>(); }
        else             { cp_wait<0>(); }
        __syncthreads();

#pragma unroll
        for (int s = 0; s < 2; s++) {        // two k16 steps within BK=32
            uint32_t af[4][4], bf[2][4];
#pragma unroll
            for (int i = 0; i < 4; i++) {
                uint32_t addr = sA[b] + (uint32_t)((wm0 + i * 16 + (lane & 15)) * ROWB
                               + s * 32 + (lane >> 4) * 16);
                ldm_x4(af[i], addr);
            }
#pragma unroll
            for (int j = 0; j < 2; j++) {
                int grp = lane >> 3;
                int row = wn0 + j * 16 + (grp >> 1) * 8 + (lane & 7);
                uint32_t addr = sB[b] + (uint32_t)(row * ROWB + s * 32 + (grp & 1) * 16);
                ldm_x4(bf[j], addr);
            }
#pragma unroll
            for (int i = 0; i < 4; i++)
#pragma unroll
                for (int jj = 0; jj < 4; jj++)
                    mma16816(acc[i][jj], af[i], &bf[jj >> 1][(jj & 1) * 2]);
        }
        __syncthreads();
    }

    // Epilogue: direct fp32 stores (float2 per fragment half)
#pragma unroll
    for (int i = 0; i < 4; i++) {
        int row = m0 + wm0 + i * 16 + (lane >> 2);
#pragma unroll
        for (int jj = 0; jj < 4; jj++) {
            int col = n0 + wn0 + jj * 8 + (lane & 3) * 2;
            float2 v0 = make_float2(acc[i][jj][0], acc[i][jj][1]);
            float2 v1 = make_float2(acc[i][jj][2], acc[i][jj][3]);
            if (BIAS) {
                float b0 = bias[col], b1 = bias[col + 1];
                v0.x += b0; v0.y += b1; v1.x += b0; v1.y += b1;
            }
            *(float2*)&C[(size_t)row * N + col] = v0;
            *(float2*)&C[(size_t)(row + 8) * N + col] = v1;
        }
    }
}

// ---------------------------------------------------------------------------
// Causal flash attention, fp32 (unchanged — next round's target).
// ---------------------------------------------------------------------------
#define ATTN_SMEM ((64 * 64 + 64 * 64 + 128 * 65) * 4)

__global__ void __launch_bounds__(128)
attn_kernel(const float* __restrict__ Qg, const float* __restrict__ Kg,
            const float* __restrict__ Vg, float* __restrict__ Og)
{
    extern __shared__ float smem[];
    float* Ks = smem;
    float* Vs = smem + 64 * 64;
    float* Ss = smem + 2 * 64 * 64;

    const int h  = blockIdx.y;
    const int qb = blockIdx.x;
    const int r  = threadIdx.x;
    const int qg = qb * 128 + r;
    const float beta = 0.125f;

    float4 q[16], o[16];
    const float* qptr = Qg + (size_t)qg * DIM + h * DHEAD;
#pragma unroll
    for (int i = 0; i < 16; i++) {
        float4 t = *(const float4*)&qptr[i * 4];
        t.x *= beta; t.y *= beta; t.z *= beta; t.w *= beta;
        q[i] = t;
        o[i] = make_float4(0.f, 0.f, 0.f, 0.f);
    }

    float m = -1e30f, l = 0.f;
    float* Srow = Ss + r * 65;

    const int nkb = qb * 2 + 2;
    for (int kb = 0; kb < nkb; kb++) {
        const int j0 = kb * 64;

        __syncthreads();
#pragma unroll
        for (int i = 0; i < 8; i++) {
            int f4  = threadIdx.x + i * 128;
            int row = f4 >> 4;
            int c4  = f4 & 15;
            *(float4*)&Ks[row * 64 + c4 * 4] =
                *(const float4*)&Kg[(size_t)(j0 + row) * DIM + h * DHEAD + c4 * 4];
            *(float4*)&Vs[row * 64 + c4 * 4] =
                *(const float4*)&Vg[(size_t)(j0 + row) * DIM + h * DHEAD + c4 * 4];
        }
        __syncthreads();

        if (qg >= j0) {
            const bool full = (j0 + 63 <= qg);
            float mb = -1e30f;
#pragma unroll 4
            for (int j = 0; j < 64; j++) {
                float s;
                if (full || (j0 + j) <= qg) {
                    float a0 = 0.f, a1 = 0.f, a2 = 0.f, a3 = 0.f;
                    const float* kr = Ks + j * 64;
#pragma unroll
                    for (int i = 0; i < 16; i++) {
                        float4 kk = *(const float4*)&kr[i * 4];
                        a0 += q[i].x * kk.x;
                        a1 += q[i].y * kk.y;
                        a2 += q[i].z * kk.z;
                        a3 += q[i].w * kk.w;
                    }
                    s = (a0 + a1) + (a2 + a3);
                } else {
                    s = -1e30f;
                }
                Srow[j] = s;
                mb = fmaxf(mb, s);
            }

            const float mnew = fmaxf(m, mb);
            const float csc = __expf(m - mnew);
            m = mnew;
            l *= csc;
#pragma unroll
            for (int i = 0; i < 16; i++) {
                o[i].x *= csc; o[i].y *= csc; o[i].z *= csc; o[i].w *= csc;
            }

#pragma unroll 2
            for (int j = 0; j < 64; j++) {
                float p = __expf(Srow[j] - mnew);
                l += p;
                const float* vr = Vs + j * 64;
#pragma unroll
                for (int i = 0; i < 16; i++) {
                    float4 vv = *(const float4*)&vr[i * 4];
                    o[i].x += p * vv.x;
                    o[i].y += p * vv.y;
                    o[i].z += p * vv.z;
                    o[i].w += p * vv.w;
                }
            }
        }
    }

    const float inv = 1.f / l;
    float* optr = Og + (size_t)qg * DIM + h * DHEAD;
#pragma unroll
    for (int i = 0; i < 16; i++) {
        float4 t = o[i];
        t.x *= inv; t.y *= inv; t.z *= inv; t.w *= inv;
        *(float4*)&optr[i * 4] = t;
    }
}

// ---------------------------------------------------------------------------
extern "C" void kernel_launch(void* const* d_in, const int* in_sizes, int n_in,
                              void* d_out, int out_size)
{
    const float* x  = (const float*)d_in[0];
    const float* Wq = (const float*)d_in[1];
    const float* Wk = (const float*)d_in[2];
    const float* Wv = (const float*)d_in[3];
    const float* Wo = (const float*)d_in[4];
    const float* bo = (const float*)d_in[5];
    float* out = (float*)d_out;

    float *Qb, *Kb, *Vb, *Ob;
    __nv_bfloat16 *XS, *WTq, *WTk, *WTv, *WTo, *OS;
    cudaGetSymbolAddress((void**)&Qb, g_Q);
    cudaGetSymbolAddress((void**)&Kb, g_K);
    cudaGetSymbolAddress((void**)&Vb, g_V);
    cudaGetSymbolAddress((void**)&Ob, g_O);
    cudaGetSymbolAddress((void**)&XS, g_XS);
    cudaGetSymbolAddress((void**)&WTq, g_WTq);
    cudaGetSymbolAddress((void**)&WTk, g_WTk);
    cudaGetSymbolAddress((void**)&WTv, g_WTv);
    cudaGetSymbolAddress((void**)&WTo, g_WTo);
    cudaGetSymbolAddress((void**)&OS, g_OS);

    cudaFuncSetAttribute(attn_kernel,
                         cudaFuncAttributeMaxDynamicSharedMemorySize, ATTN_SMEM);

    dim3 wgrid(DIM / 32, DIM / 32);     // (32, 32) transpose-split tiles
    split_w_kernel<<<wgrid, 256>>>(Wq, WTq, DIM, DIM);
    split_w_kernel<<<wgrid, 256>>>(Wk, WTk, DIM, DIM);
    split_w_kernel<<<wgrid, 256>>>(Wv, WTv, DIM, DIM);
    split_w_kernel<<<wgrid, 256>>>(Wv, WTv, DIM, DIM);
    split_w_kernel<<<wgrid, 256>>>(Wo, WTo, DIM, DIM);

    split_a_kernel<<<(SEQ * DIM) / (256 * 4), 256>>>(x, XS, DIM);

    dim3 ggrid(DIM / 128, SEQ / 128);   // (8, 32)
    gemm_mma_kernel<false><<<ggrid, 256>>>(XS, WTq, nullptr, Qb, DIM);
    gemm_mma_kernel<false><<<ggrid, 256>>>(XS, WTk, nullptr, Kb, DIM);
    gemm_mma_kernel<false><<<ggrid, 256>>>(XS, WTv, nullptr, Vb, DIM);

    dim3 agrid(SEQ / 128, HEADS);       // (32, 16)
    attn_kernel<<<agrid, 128, ATTN_SMEM>>>(Qb, Kb, Vb, Ob);

    split_a_kernel<<<(SEQ * DIM) / (256 * 4), 256>>>(Ob, OS, DIM);
    gemm_mma_kernel<true><<<ggrid, 256>>>(OS, WTo, bo, out, DIM);
}

// round 7
// speedup vs baseline: 3.8155x; 3.1480x over previous
#include <cuda_runtime.h>
#include <cuda_bf16.h>
#include <cuda_fp16.h>
#include <math.h>
#include <stdint.h>

#define SEQ    4096
#define DIM    1024
#define HEADS  16
#define DHEAD  64
#define KP     (3 * DIM)          // split-K': [hi|hi|lo] / [hi|lo|hi]
#define BK     32
#define NIT    (KP / BK)          // 96

// ---------------- scratch (__device__ globals; no allocs allowed) ----------
__device__ float g_Q[SEQ * DIM];
__device__ float g_K[SEQ * DIM];
__device__ float g_V[SEQ * DIM];
__device__ float g_O[SEQ * DIM];
__device__ __nv_bfloat16 g_XS[SEQ * KP];
__device__ __nv_bfloat16 g_WTq[DIM * KP];
__device__ __nv_bfloat16 g_WTk[DIM * KP];
__device__ __nv_bfloat16 g_WTv[DIM * KP];
__device__ __nv_bfloat16 g_WTo[DIM * KP];
__device__ __nv_bfloat16 g_OS[SEQ * KP];

// ---------------- helpers (non-arch-specific PTX, sm_80+) ------------------
__device__ __forceinline__ uint32_t smem_u32(const void* p) {
    return (uint32_t)__cvta_generic_to_shared(p);
}
__device__ __forceinline__ void cp16(uint32_t dst, const void* src) {
    asm volatile("cp.async.cg.shared.global [%0], [%1], 16;"
                 :: "r"(dst), "l"(src) : "memory");
}
__device__ __forceinline__ void cp_commit() {
    asm volatile("cp.async.commit_group;" ::: "memory");
}
template <int N>
__device__ __forceinline__ void cp_wait() {
    asm volatile("cp.async.wait_group %0;" :: "n"(N) : "memory");
}
__device__ __forceinline__ void ldm_x4(uint32_t* r, uint32_t addr) {
    asm volatile("ldmatrix.sync.aligned.m8n8.x4.shared.b16 {%0,%1,%2,%3}, [%4];"
                 : "=r"(r[0]), "=r"(r[1]), "=r"(r[2]), "=r"(r[3]) : "r"(addr));
}
__device__ __forceinline__ void ldm_x4t(uint32_t* r, uint32_t addr) {
    asm volatile("ldmatrix.sync.aligned.m8n8.x4.trans.shared.b16 {%0,%1,%2,%3}, [%4];"
                 : "=r"(r[0]), "=r"(r[1]), "=r"(r[2]), "=r"(r[3]) : "r"(addr));
}
__device__ __forceinline__ void mma16816(float* c, const uint32_t* a,
                                         const uint32_t* b) {
    asm volatile("mma.sync.aligned.m16n8k16.row.col.f32.bf16.bf16.f32 "
                 "{%0,%1,%2,%3}, {%4,%5,%6,%7}, {%8,%9}, {%0,%1,%2,%3};"
                 : "+f"(c[0]), "+f"(c[1]), "+f"(c[2]), "+f"(c[3])
                 : "r"(a[0]), "r"(a[1]), "r"(a[2]), "r"(a[3]),
                   "r"(b[0]), "r"(b[1]));
}
__device__ __forceinline__ void mma16816h(float* c, const uint32_t* a,
                                          uint32_t b0, uint32_t b1) {
    asm volatile("mma.sync.aligned.m16n8k16.row.col.f32.f16.f16.f32 "
                 "{%0,%1,%2,%3}, {%4,%5,%6,%7}, {%8,%9}, {%0,%1,%2,%3};"
                 : "+f"(c[0]), "+f"(c[1]), "+f"(c[2]), "+f"(c[3])
                 : "r"(a[0]), "r"(a[1]), "r"(a[2]), "r"(a[3]),
                   "r"(b0), "r"(b1));
}
// exp2 of two fp32 values -> packed fp16x2 {lo=exp2(lo), hi=exp2(hi)}
__device__ __forceinline__ uint32_t exp2_f16x2(float lo, float hi) {
    uint32_t hreg, p;
    asm volatile("cvt.rn.f16x2.f32 %0, %1, %2;" : "=r"(hreg) : "f"(hi), "f"(lo));
    asm volatile("ex2.approx.f16x2 %0, %1;" : "=r"(p) : "r"(hreg));
    return p;
}
__device__ __forceinline__ float ex2f(float x) {
    float y; asm volatile("ex2.approx.f32 %0, %1;" : "=f"(y) : "f"(x)); return y;
}

// ---------------------------------------------------------------------------
// Split conversions for fp32 emulation via bf16 (GEMM inputs)
// ---------------------------------------------------------------------------
__global__ void __launch_bounds__(256)
split_a_kernel(const float* __restrict__ X, __nv_bfloat16* __restrict__ XS, int K)
{
    int idx = (blockIdx.x * 256 + threadIdx.x) * 4;
    int m = idx / K, k = idx % K;
    float4 v = *(const float4*)(X + idx);
    __nv_bfloat16 h0 = __float2bfloat16(v.x), h1 = __float2bfloat16(v.y);
    __nv_bfloat16 h2 = __float2bfloat16(v.z), h3 = __float2bfloat16(v.w);
    __nv_bfloat16 l0 = __float2bfloat16(v.x - __bfloat162float(h0));
    __nv_bfloat16 l1 = __float2bfloat16(v.y - __bfloat162float(h1));
    __nv_bfloat16 l2 = __float2bfloat16(v.z - __bfloat162float(h2));
    __nv_bfloat16 l3 = __float2bfloat16(v.w - __bfloat162float(h3));
    __nv_bfloat162 hA = __nv_bfloat162(h0, h1), hB = __nv_bfloat162(h2, h3);
    __nv_bfloat162 lA = __nv_bfloat162(l0, l1), lB = __nv_bfloat162(l2, l3);
    __nv_bfloat162* base = (__nv_bfloat162*)(XS + (size_t)m * (3 * K) + k);
    base[0] = hA; base[1] = hB;
    base[K / 2] = hA; base[K / 2 + 1] = hB;
    base[K] = lA; base[K + 1] = lB;
}

__global__ void __launch_bounds__(256)
split_w_kernel(const float* __restrict__ W, __nv_bfloat16* __restrict__ WT, int K, int N)
{
    __shared__ float t[32][33];
    const int tx = threadIdx.x & 31, ty = threadIdx.x >> 5;
    const int k0 = blockIdx.y * 32, n0 = blockIdx.x * 32;
#pragma unroll
    for (int i = 0; i < 4; i++)
        t[ty + i * 8][tx] = W[(size_t)(k0 + ty + i * 8) * N + n0 + tx];
    __syncthreads();
#pragma unroll
    for (int i = 0; i < 4; i++) {
        float v = t[tx][ty + i * 8];
        __nv_bfloat16 h = __float2bfloat16(v);
        __nv_bfloat16 l = __float2bfloat16(v - __bfloat162float(h));
        int n = n0 + ty + i * 8;
        __nv_bfloat16* row = WT + (size_t)n * (3 * K);
        row[k0 + tx] = h;
        row[K + k0 + tx] = l;
        row[2 * K + k0 + tx] = h;
    }
}

// ---------------------------------------------------------------------------
// HMMA GEMM (TN), unchanged from R6 (passed @ rel_err 1e-5)
// ---------------------------------------------------------------------------
#define ROWB   80
#define TILEB  (128 * ROWB)

template <bool BIAS>
__global__ void __launch_bounds__(256, 2)
gemm_mma_kernel(const __nv_bfloat16* __restrict__ A,
                const __nv_bfloat16* __restrict__ Bt,
                const float* __restrict__ bias, float* __restrict__ C, int N)
{
    __shared__ __align__(128) char smem[4 * TILEB];

    const int tid  = threadIdx.x;
    const int lane = tid & 31, wid = tid >> 5;
    const int wm0  = (wid & 1) * 64;
    const int wn0  = (wid >> 1) * 32;
    const int m0 = blockIdx.y * 128, n0 = blockIdx.x * 128;

    const uint32_t sbase = smem_u32(smem);
    const uint32_t sA[2] = { sbase,             sbase + TILEB };
    const uint32_t sB[2] = { sbase + 2 * TILEB, sbase + 3 * TILEB };

    float acc[4][4][4];
#pragma unroll
    for (int i = 0; i < 4; i++)
#pragma unroll
        for (int j = 0; j < 4; j++)
#pragma unroll
            for (int r = 0; r < 4; r++) acc[i][j][r] = 0.f;

    const int lrow = tid >> 2, lc16 = tid & 3;
    auto load_tile = [&](int c, int b) {
        const int kc0 = c * BK;
#pragma unroll
        for (int i = 0; i < 2; i++) {
            int row = lrow + i * 64;
            uint32_t so = (uint32_t)(row * ROWB + lc16 * 16);
            cp16(sA[b] + so, A  + (size_t)(m0 + row) * KP + kc0 + lc16 * 8);
            cp16(sB[b] + so, Bt + (size_t)(n0 + row) * KP + kc0 + lc16 * 8);
        }
        cp_commit();
    };

    load_tile(0, 0);

    for (int c = 0; c < NIT; c++) {
        const int b = c & 1;
        if (c + 1 < NIT) { load_tile(c + 1, b ^ 1); cp_wait<1>(); }
        else             { cp_wait<0>(); }
        __syncthreads();

#pragma unroll
        for (int s = 0; s < 2; s++) {
            uint32_t af[4][4], bf[2][4];
#pragma unroll
            for (int i = 0; i < 4; i++) {
                uint32_t addr = sA[b] + (uint32_t)((wm0 + i * 16 + (lane & 15)) * ROWB
                               + s * 32 + (lane >> 4) * 16);
                ldm_x4(af[i], addr);
            }
#pragma unroll
            for (int j = 0; j < 2; j++) {
                int grp = lane >> 3;
                int row = wn0 + j * 16 + (grp >> 1) * 8 + (lane & 7);
                uint32_t addr = sB[b] + (uint32_t)(row * ROWB + s * 32 + (grp & 1) * 16);
                ldm_x4(bf[j], addr);
            }
#pragma unroll
            for (int i = 0; i < 4; i++)
#pragma unroll
                for (int jj = 0; jj < 4; jj++)
                    mma16816(acc[i][jj], af[i], &bf[jj >> 1][(jj & 1) * 2]);
        }
        __syncthreads();
    }

#pragma unroll
    for (int i = 0; i < 4; i++) {
        int row = m0 + wm0 + i * 16 + (lane >> 2);
#pragma unroll
        for (int jj = 0; jj < 4; jj++) {
            int col = n0 + wn0 + jj * 8 + (lane & 3) * 2;
            float2 v0 = make_float2(acc[i][jj][0], acc[i][jj][1]);
            float2 v1 = make_float2(acc[i][jj][2], acc[i][jj][3]);
            if (BIAS) {
                float b0 = bias[col], b1 = bias[col + 1];
                v0.x += b0; v0.y += b1; v1.x += b0; v1.y += b1;
            }
            *(float2*)&C[(size_t)row * N + col] = v0;
            *(float2*)&C[(size_t)(row + 8) * N + col] = v1;
        }
    }
}

// ---------------------------------------------------------------------------
// HMMA flash attention (causal).
// Grid (32, 16): CTA = 128 q-rows (reversed order) x 1 head, 256 thr, 8 warps,
// each warp one m16 row-slab. QK = 3-pass bf16 hi/lo split (exact to ~2^-16),
// base-2 online softmax via ex2.approx.f16x2, PV in fp16 with P fragments
// repacked in registers (FA2), row-sums via ones-column MMA.
// ---------------------------------------------------------------------------
#define PADK     72
#define PADB     (PADK * 2)
#define ATT_SMEM ((2 * 128 * PADK + 2 * 64 * PADK + 64 * PADK) * 2)

__global__ void __launch_bounds__(256)
attn_mma_kernel(const float* __restrict__ Qg, const float* __restrict__ Kg,
                const float* __restrict__ Vg, float* __restrict__ Og)
{
    extern __shared__ __align__(16) char sraw[];
    __nv_bfloat16* Qhi = (__nv_bfloat16*)sraw;
    __nv_bfloat16* Qlo = Qhi + 128 * PADK;
    __nv_bfloat16* Khi = Qlo + 128 * PADK;
    __nv_bfloat16* Klo = Khi + 64 * PADK;
    __half*        Vh  = (__half*)(Klo + 64 * PADK);

    const int h   = blockIdx.y;
    const int qb  = (int)gridDim.x - 1 - (int)blockIdx.x;
    const int tid = threadIdx.x, lane = tid & 31, wid = tid >> 5;
    const int q0  = qb * 128;
    const float SC = 0.125f * 1.4426950408889634f;   // beta * log2(e)

    // Load Q, scale, split hi/lo
    for (int c = tid; c < 128 * 16; c += 256) {
        int row = c >> 4, col = (c & 15) * 4;
        float4 v = *(const float4*)&Qg[(size_t)(q0 + row) * DIM + h * DHEAD + col];
        float f[4] = { v.x * SC, v.y * SC, v.z * SC, v.w * SC };
#pragma unroll
        for (int i = 0; i < 4; i++) {
            __nv_bfloat16 hi = __float2bfloat16(f[i]);
            Qhi[row * PADK + col + i] = hi;
            Qlo[row * PADK + col + i] = __float2bfloat16(f[i] - __bfloat162float(hi));
        }
    }
    __syncthreads();

    // Hoist Q fragments (4 ksteps x 4 regs, hi+lo)
    uint32_t aHi[4][4], aLo[4][4];
    {
        const uint32_t qhb = smem_u32(Qhi), qlb = smem_u32(Qlo);
        const uint32_t aoff = (uint32_t)((wid * 16 + (lane & 15)) * PADB + (lane >> 4) * 16);
#pragma unroll
        for (int t = 0; t < 4; t++) {
            ldm_x4(aHi[t], qhb + aoff + t * 32);
            ldm_x4(aLo[t], qlb + aoff + t * 32);
        }
    }

    float o[8][4], lf[4];
#pragma unroll
    for (int g = 0; g < 8; g++)
#pragma unroll
        for (int r = 0; r < 4; r++) o[g][r] = 0.f;
#pragma unroll
    for (int r = 0; r < 4; r++) lf[r] = 0.f;
    float m0 = -1e30f, m1 = -1e30f;

    const uint32_t khb = smem_u32(Khi), klb = smem_u32(Klo), vhb = smem_u32(Vh);
    const int grp = lane >> 3;
    const uint32_t bRowOff = (uint32_t)(((grp >> 1) * 8 + (lane & 7)) * PADB + (grp & 1) * 16);
    const uint32_t vRowOff = (uint32_t)((((lane & 7) + 8 * (grp & 1))) * PADB + (lane >> 4) * 16);

    const int nkb = qb * 2 + 2;
    for (int kb = 0; kb < nkb; kb++) {
        const int j0 = kb * 64;
        __syncthreads();
        // Load + convert K (hi/lo bf16) and V (fp16)
#pragma unroll
        for (int i = 0; i < 4; i++) {
            int c = tid + i * 256;               // 0..1023
            int row = c >> 4, col = (c & 15) * 4;
            float4 kv = *(const float4*)&Kg[(size_t)(j0 + row) * DIM + h * DHEAD + col];
            float4 vv = *(const float4*)&Vg[(size_t)(j0 + row) * DIM + h * DHEAD + col];
            float kf[4] = { kv.x, kv.y, kv.z, kv.w };
            float vf[4] = { vv.x, vv.y, vv.z, vv.w };
#pragma unroll
            for (int u = 0; u < 4; u++) {
                __nv_bfloat16 hi = __float2bfloat16(kf[u]);
                Khi[row * PADK + col + u] = hi;
                Klo[row * PADK + col + u] = __float2bfloat16(kf[u] - __bfloat162float(hi));
                Vh[row * PADK + col + u]  = __float2half(vf[u]);
            }
        }
        __syncthreads();

        if (q0 + wid * 16 + 15 < j0) continue;   // warp fully masked

        // S = Q'.K'^T : 3 split passes
        float s[8][4];
#pragma unroll
        for (int g = 0; g < 8; g++)
#pragma unroll
            for (int r = 0; r < 4; r++) s[g][r] = 0.f;

#pragma unroll
        for (int pass = 0; pass < 3; pass++) {
            const uint32_t bb = (pass == 1) ? klb : khb;
#pragma unroll
            for (int t = 0; t < 4; t++) {
                const uint32_t* a = (pass < 2) ? aHi[t] : aLo[t];
#pragma unroll
                for (int g = 0; g < 4; g++) {
                    uint32_t bq[4];
                    ldm_x4(bq, bb + (uint32_t)(g * 16 * PADB + t * 32) + bRowOff);
                    mma16816(s[g * 2],     a, &bq[0]);
                    mma16816(s[g * 2 + 1], a, &bq[2]);
                }
            }
        }

        const int r0 = q0 + wid * 16 + (lane >> 2);
        const int r1 = r0 + 8;

        // Causal mask (diag spans last two key blocks)
        if (kb >= nkb - 2) {
            const int cb = j0 + (lane & 3) * 2;
#pragma unroll
            for (int g = 0; g < 8; g++) {
                int c0 = cb + g * 8;
                if (c0 > r0)     s[g][0] = -1e30f;
                if (c0 + 1 > r0) s[g][1] = -1e30f;
                if (c0 > r1)     s[g][2] = -1e30f;
                if (c0 + 1 > r1) s[g][3] = -1e30f;
            }
        }

        // Row max (base-2 units)
        float mx0 = -1e30f, mx1 = -1e30f;
#pragma unroll
        for (int g = 0; g < 8; g++) {
            mx0 = fmaxf(mx0, fmaxf(s[g][0], s[g][1]));
            mx1 = fmaxf(mx1, fmaxf(s[g][2], s[g][3]));
        }
        mx0 = fmaxf(mx0, __shfl_xor_sync(0xffffffffu, mx0, 1));
        mx0 = fmaxf(mx0, __shfl_xor_sync(0xffffffffu, mx0, 2));
        mx1 = fmaxf(mx1, __shfl_xor_sync(0xffffffffu, mx1, 1));
        mx1 = fmaxf(mx1, __shfl_xor_sync(0xffffffffu, mx1, 2));

        const float mn0 = fmaxf(m0, mx0), mn1 = fmaxf(m1, mx1);
        const float cs0 = ex2f(m0 - mn0), cs1 = ex2f(m1 - mn1);
        m0 = mn0; m1 = mn1;
#pragma unroll
        for (int g = 0; g < 8; g++) {
            o[g][0] *= cs0; o[g][1] *= cs0; o[g][2] *= cs1; o[g][3] *= cs1;
        }
        lf[0] *= cs0; lf[1] *= cs0; lf[2] *= cs1; lf[3] *= cs1;

        // P = exp2(s - m) in fp16x2, packed directly into A-fragments
        uint32_t pa[4][4];
#pragma unroll
        for (int g = 0; g < 8; g++) {
            uint32_t p01 = exp2_f16x2(s[g][0] - mn0, s[g][1] - mn0);
            uint32_t p23 = exp2_f16x2(s[g][2] - mn1, s[g][3] - mn1);
            if ((g & 1) == 0) { pa[g >> 1][0] = p01; pa[g >> 1][1] = p23; }
            else              { pa[g >> 1][2] = p01; pa[g >> 1][3] = p23; }
        }

        // O += P.V (fp16), l += P.1 via ones-column MMA
        const uint32_t ONES = 0x3C003C00u;
#pragma unroll
        for (int t = 0; t < 4; t++) {
#pragma unroll
            for (int g = 0; g < 4; g++) {
                uint32_t bv[4];
                ldm_x4t(bv, vhb + (uint32_t)(t * 16 * PADB + g * 32) + vRowOff);
                mma16816h(o[g * 2],     pa[t], bv[0], bv[1]);
                mma16816h(o[g * 2 + 1], pa[t], bv[2], bv[3]);
            }
            mma16816h(lf, pa[t], ONES, ONES);
        }
    }

    // Epilogue
    const float inv0 = 1.f / lf[0], inv1 = 1.f / lf[2];
    const int r0 = q0 + wid * 16 + (lane >> 2);
    const int colb = h * DHEAD + (lane & 3) * 2;
#pragma unroll
    for (int g = 0; g < 8; g++) {
        int col = colb + g * 8;
        *(float2*)&Og[(size_t)r0 * DIM + col] =
            make_float2(o[g][0] * inv0, o[g][1] * inv0);
        *(float2*)&Og[(size_t)(r0 + 8) * DIM + col] =
            make_float2(o[g][2] * inv1, o[g][3] * inv1);
    }
}

// ---------------------------------------------------------------------------
extern "C" void kernel_launch(void* const* d_in, const int* in_sizes, int n_in,
                              void* d_out, int out_size)
{
    const float* x  = (const float*)d_in[0];
    const float* Wq = (const float*)d_in[1];
    const float* Wk = (const float*)d_in[2];
    const float* Wv = (const float*)d_in[3];
    const float* Wo = (const float*)d_in[4];
    const float* bo = (const float*)d_in[5];
    float* out = (float*)d_out;

    float *Qb, *Kb, *Vb, *Ob;
    __nv_bfloat16 *XS, *WTq, *WTk, *WTv, *WTo, *OS;
    cudaGetSymbolAddress((void**)&Qb, g_Q);
    cudaGetSymbolAddress((void**)&Kb, g_K);
    cudaGetSymbolAddress((void**)&Vb, g_V);
    cudaGetSymbolAddress((void**)&Ob, g_O);
    cudaGetSymbolAddress((void**)&XS, g_XS);
    cudaGetSymbolAddress((void**)&WTq, g_WTq);
    cudaGetSymbolAddress((void**)&WTk, g_WTk);
    cudaGetSymbolAddress((void**)&WTv, g_WTv);
    cudaGetSymbolAddress((void**)&WTo, g_WTo);
    cudaGetSymbolAddress((void**)&OS, g_OS);

    cudaFuncSetAttribute(attn_mma_kernel,
                         cudaFuncAttributeMaxDynamicSharedMemorySize, ATT_SMEM);

    dim3 wgrid(DIM / 32, DIM / 32);
    split_w_kernel<<<wgrid, 256>>>(Wq, WTq, DIM, DIM);
    split_w_kernel<<<wgrid, 256>>>(Wk, WTk, DIM, DIM);
    split_w_kernel<<<wgrid, 256>>>(Wv, WTv, DIM, DIM);
    split_w_kernel<<<wgrid, 256>>>(Wo, WTo, DIM, DIM);

    split_a_kernel<<<(SEQ * DIM) / (256 * 4), 256>>>(x, XS, DIM);

    dim3 ggrid(DIM / 128, SEQ / 128);
    gemm_mma_kernel<false><<<ggrid, 256>>>(XS, WTq, nullptr, Qb, DIM);
    gemm_mma_kernel<false><<<ggrid, 256>>>(XS, WTk, nullptr, Kb, DIM);
    gemm_mma_kernel<false><<<ggrid, 256>>>(XS, WTv, nullptr, Vb, DIM);

    dim3 agrid(SEQ / 128, HEADS);
    attn_mma_kernel<<<agrid, 256, ATT_SMEM>>>(Qb, Kb, Vb, Ob);

    split_a_kernel<<<(SEQ * DIM) / (256 * 4), 256>>>(Ob, OS, DIM);
    gemm_mma_kernel<true><<<ggrid, 256>>>(OS, WTo, bo, out, DIM);
}

// round 12
// speedup vs baseline: 3.9479x; 1.0347x over previous
#include <cuda_runtime.h>
#include <cuda_bf16.h>
#include <cuda_fp16.h>
#include <math.h>
#include <stdint.h>

#define SEQ    4096
#define DIM    1024
#define HEADS  16
#define DHEAD  64
#define KP     (3 * DIM)          // split-K': [hi|hi|lo] / [hi|lo|hi]
#define BK     32
#define NIT    (KP / BK)          // 96
#define SCLOG2 0.1803368801111204f   // (1/8) * log2(e)

// ---------------- scratch (__device__ globals; no allocs allowed) ----------
__device__ __nv_bfloat16 g_XS[SEQ * KP];
__device__ __nv_bfloat16 g_WTq[DIM * KP];
__device__ __nv_bfloat16 g_WTk[DIM * KP];
__device__ __nv_bfloat16 g_WTv[DIM * KP];
__device__ __nv_bfloat16 g_WTo[DIM * KP];
__device__ __nv_bfloat16 g_Qhi[SEQ * DIM];   // pre-scaled by SCLOG2
__device__ __nv_bfloat16 g_Qlo[SEQ * DIM];
__device__ __nv_bfloat16 g_Khi[SEQ * DIM];
__device__ __nv_bfloat16 g_Klo[SEQ * DIM];
__device__ __half        g_Vh [SEQ * DIM];
__device__ __nv_bfloat16 g_OS[SEQ * KP];     // attention out, split layout

// ---------------- helpers (non-arch-specific PTX, sm_80+) ------------------
__device__ __forceinline__ uint32_t smem_u32(const void* p) {
    return (uint32_t)__cvta_generic_to_shared(p);
}
__device__ __forceinline__ void cp16(uint32_t dst, const void* src) {
    asm volatile("cp.async.cg.shared.global [%0], [%1], 16;"
                 :: "r"(dst), "l"(src) : "memory");
}
__device__ __forceinline__ void cp_commit() {
    asm volatile("cp.async.commit_group;" ::: "memory");
}
template <int N>
__device__ __forceinline__ void cp_wait() {
    asm volatile("cp.async.wait_group %0;" :: "n"(N) : "memory");
}
__device__ __forceinline__ void ldm_x4(uint32_t* r, uint32_t addr) {
    asm volatile("ldmatrix.sync.aligned.m8n8.x4.shared.b16 {%0,%1,%2,%3}, [%4];"
                 : "=r"(r[0]), "=r"(r[1]), "=r"(r[2]), "=r"(r[3]) : "r"(addr));
}
__device__ __forceinline__ void ldm_x4t(uint32_t* r, uint32_t addr) {
    asm volatile("ldmatrix.sync.aligned.m8n8.x4.trans.shared.b16 {%0,%1,%2,%3}, [%4];"
                 : "=r"(r[0]), "=r"(r[1]), "=r"(r[2]), "=r"(r[3]) : "r"(addr));
}
__device__ __forceinline__ void mma16816(float* c, const uint32_t* a,
                                         const uint32_t* b) {
    asm volatile("mma.sync.aligned.m16n8k16.row.col.f32.bf16.bf16.f32 "
                 "{%0,%1,%2,%3}, {%4,%5,%6,%7}, {%8,%9}, {%0,%1,%2,%3};"
                 : "+f"(c[0]), "+f"(c[1]), "+f"(c[2]), "+f"(c[3])
                 : "r"(a[0]), "r"(a[1]), "r"(a[2]), "r"(a[3]),
                   "r"(b[0]), "r"(b[1]));
}
__device__ __forceinline__ void mma16816h(float* c, const uint32_t* a,
                                          uint32_t b0, uint32_t b1) {
    asm volatile("mma.sync.aligned.m16n8k16.row.col.f32.f16.f16.f32 "
                 "{%0,%1,%2,%3}, {%4,%5,%6,%7}, {%8,%9}, {%0,%1,%2,%3};"
                 : "+f"(c[0]), "+f"(c[1]), "+f"(c[2]), "+f"(c[3])
                 : "r"(a[0]), "r"(a[1]), "r"(a[2]), "r"(a[3]),
                   "r"(b0), "r"(b1));
}
__device__ __forceinline__ uint32_t exp2_f16x2(float lo, float hi) {
    uint32_t hreg, p;
    asm volatile("cvt.rn.f16x2.f32 %0, %1, %2;" : "=r"(hreg) : "f"(hi), "f"(lo));
    asm volatile("ex2.approx.f16x2 %0, %1;" : "=r"(p) : "r"(hreg));
    return p;
}
__device__ __forceinline__ float ex2f(float x) {
    float y; asm volatile("ex2.approx.f32 %0, %1;" : "=f"(y) : "f"(x)); return y;
}
__device__ __forceinline__ void store_bf16x2(__nv_bfloat16* p, float a, float b) {
    __nv_bfloat162 v(__float2bfloat16(a), __float2bfloat16(b));
    *(__nv_bfloat162*)p = v;
}

// ---------------------------------------------------------------------------
// Split conversions (GEMM inputs)
// ---------------------------------------------------------------------------
__global__ void __launch_bounds__(256)
split_a_kernel(const float* __restrict__ X, __nv_bfloat16* __restrict__ XS, int K)
{
    int idx = (blockIdx.x * 256 + threadIdx.x) * 4;
    int m = idx / K, k = idx % K;
    float4 v = *(const float4*)(X + idx);
    __nv_bfloat16 h0 = __float2bfloat16(v.x), h1 = __float2bfloat16(v.y);
    __nv_bfloat16 h2 = __float2bfloat16(v.z), h3 = __float2bfloat16(v.w);
    __nv_bfloat16 l0 = __float2bfloat16(v.x - __bfloat162float(h0));
    __nv_bfloat16 l1 = __float2bfloat16(v.y - __bfloat162float(h1));
    __nv_bfloat16 l2 = __float2bfloat16(v.z - __bfloat162float(h2));
    __nv_bfloat16 l3 = __float2bfloat16(v.w - __bfloat162float(h3));
    __nv_bfloat162 hA = __nv_bfloat162(h0, h1), hB = __nv_bfloat162(h2, h3);
    __nv_bfloat162 lA = __nv_bfloat162(l0, l1), lB = __nv_bfloat162(l2, l3);
    __nv_bfloat162* base = (__nv_bfloat162*)(XS + (size_t)m * (3 * K) + k);
    base[0] = hA; base[1] = hB;
    base[K / 2] = hA; base[K / 2 + 1] = hB;
    base[K] = lA; base[K + 1] = lB;
}

__global__ void __launch_bounds__(256)
split_w_kernel(const float* __restrict__ W, __nv_bfloat16* __restrict__ WT, int K, int N)
{
    __shared__ float t[32][33];
    const int tx = threadIdx.x & 31, ty = threadIdx.x >> 5;
    const int k0 = blockIdx.y * 32, n0 = blockIdx.x * 32;
#pragma unroll
    for (int i = 0; i < 4; i++)
        t[ty + i * 8][tx] = W[(size_t)(k0 + ty + i * 8) * N + n0 + tx];
    __syncthreads();
#pragma unroll
    for (int i = 0; i < 4; i++) {
        float v = t[tx][ty + i * 8];
        __nv_bfloat16 h = __float2bfloat16(v);
        __nv_bfloat16 l = __float2bfloat16(v - __bfloat162float(h));
        int n = n0 + ty + i * 8;
        __nv_bfloat16* row = WT + (size_t)n * (3 * K);
        row[k0 + tx] = h;
        row[K + k0 + tx] = l;
        row[2 * K + k0 + tx] = h;
    }
}

// ---------------------------------------------------------------------------
// HMMA GEMM (TN). MODE: 0 = Q (scale+split bf16), 1 = K (split bf16),
// 2 = V (fp16), 3 = fp32 + bias.
// ---------------------------------------------------------------------------
#define ROWB   80
#define TILEB  (128 * ROWB)

template <int MODE>
__global__ void __launch_bounds__(256, 2)
gemm_mma_kernel(const __nv_bfloat16* __restrict__ A,
                const __nv_bfloat16* __restrict__ Bt,
                const float* __restrict__ bias, float* __restrict__ C,
                __nv_bfloat16* __restrict__ Ohi, __nv_bfloat16* __restrict__ Olo,
                __half* __restrict__ Oh, int N)
{
    __shared__ __align__(128) char smem[4 * TILEB];

    const int tid  = threadIdx.x;
    const int lane = tid & 31, wid = tid >> 5;
    const int wm0  = (wid & 1) * 64;
    const int wn0  = (wid >> 1) * 32;
    const int m0 = blockIdx.y * 128, n0 = blockIdx.x * 128;

    const uint32_t sbase = smem_u32(smem);
    const uint32_t sA[2] = { sbase,             sbase + TILEB };
    const uint32_t sB[2] = { sbase + 2 * TILEB, sbase + 3 * TILEB };

    float acc[4][4][4];
#pragma unroll
    for (int i = 0; i < 4; i++)
#pragma unroll
        for (int j = 0; j < 4; j++)
#pragma unroll
            for (int r = 0; r < 4; r++) acc[i][j][r] = 0.f;

    const int lrow = tid >> 2, lc16 = tid & 3;
    auto load_tile = [&](int c, int b) {
        const int kc0 = c * BK;
#pragma unroll
        for (int i = 0; i < 2; i++) {
            int row = lrow + i * 64;
            uint32_t so = (uint32_t)(row * ROWB + lc16 * 16);
            cp16(sA[b] + so, A  + (size_t)(m0 + row) * KP + kc0 + lc16 * 8);
            cp16(sB[b] + so, Bt + (size_t)(n0 + row) * KP + kc0 + lc16 * 8);
        }
        cp_commit();
    };

    load_tile(0, 0);

    for (int c = 0; c < NIT; c++) {
        const int b = c & 1;
        if (c + 1 < NIT) { load_tile(c + 1, b ^ 1); cp_wait<1>(); }
        else             { cp_wait<0>(); }
        __syncthreads();

#pragma unroll
        for (int s = 0; s < 2; s++) {
            uint32_t af[4][4], bf[2][4];
#pragma unroll
            for (int i = 0; i < 4; i++) {
                uint32_t addr = sA[b] + (uint32_t)((wm0 + i * 16 + (lane & 15)) * ROWB
                               + s * 32 + (lane >> 4) * 16);
                ldm_x4(af[i], addr);
            }
#pragma unroll
            for (int j = 0; j < 2; j++) {
                int grp = lane >> 3;
                int row = wn0 + j * 16 + (grp >> 1) * 8 + (lane & 7);
                uint32_t addr = sB[b] + (uint32_t)(row * ROWB + s * 32 + (grp & 1) * 16);
                ldm_x4(bf[j], addr);
            }
#pragma unroll
            for (int i = 0; i < 4; i++)
#pragma unroll
                for (int jj = 0; jj < 4; jj++)
                    mma16816(acc[i][jj], af[i], &bf[jj >> 1][(jj & 1) * 2]);
        }
        __syncthreads();
    }

#pragma unroll
    for (int i = 0; i < 4; i++) {
        int row = m0 + wm0 + i * 16 + (lane >> 2);
#pragma unroll
        for (int jj = 0; jj < 4; jj++) {
            int col = n0 + wn0 + jj * 8 + (lane & 3) * 2;
            float v[4] = { acc[i][jj][0], acc[i][jj][1],
                           acc[i][jj][2], acc[i][jj][3] };
            if (MODE == 3) {
                float b0 = bias[col], b1 = bias[col + 1];
                *(float2*)&C[(size_t)row * N + col] =
                    make_float2(v[0] + b0, v[1] + b1);
                *(float2*)&C[(size_t)(row + 8) * N + col] =
                    make_float2(v[2] + b0, v[3] + b1);
            } else if (MODE == 2) {
                *(__half2*)&Oh[(size_t)row * N + col] =
                    __floats2half2_rn(v[0], v[1]);
                *(__half2*)&Oh[(size_t)(row + 8) * N + col] =
                    __floats2half2_rn(v[2], v[3]);
            } else {
                if (MODE == 0) {
#pragma unroll
                    for (int r = 0; r < 4; r++) v[r] *= SCLOG2;
                }
                float h_[4], l_[4];
#pragma unroll
                for (int r = 0; r < 4; r++) {
                    h_[r] = __bfloat162float(__float2bfloat16(v[r]));
                    l_[r] = v[r] - h_[r];
                }
                store_bf16x2(&Ohi[(size_t)row * N + col],       h_[0], h_[1]);
                store_bf16x2(&Ohi[(size_t)(row + 8) * N + col], h_[2], h_[3]);
                store_bf16x2(&Olo[(size_t)row * N + col],       l_[0], l_[1]);
                store_bf16x2(&Olo[(size_t)(row + 8) * N + col], l_[2], l_[3]);
            }
        }
    }
}

// ---------------------------------------------------------------------------
// HMMA flash attention (causal). Inputs pre-split bf16 (Q scaled) / fp16 V.
// cp.async double-buffered K/V stages. Output written directly in split
// [hi|hi|lo] layout to OS.
// ---------------------------------------------------------------------------
#define PADK     72
#define PADB     144
#define QBYTES   (128 * PADB)                 // 18432
#define KTILEB   (64 * PADB)                  // 9216
#define STAGEB   (3 * KTILEB)                 // 27648
#define ATT_SMEM (2 * QBYTES + 2 * STAGEB)    // 92160

__global__ void __launch_bounds__(256)
attn_mma_kernel(const __nv_bfloat16* __restrict__ Qhi_g,
                const __nv_bfloat16* __restrict__ Qlo_g,
                const __nv_bfloat16* __restrict__ Khi_g,
                const __nv_bfloat16* __restrict__ Klo_g,
                const __half* __restrict__ Vh_g,
                __nv_bfloat16* __restrict__ OS)
{
    extern __shared__ __align__(16) char sraw[];
    const uint32_t sbase = smem_u32(sraw);
    const uint32_t qhb = sbase, qlb = sbase + QBYTES;
    const uint32_t stg = sbase + 2 * QBYTES;

    const int h   = blockIdx.y;
    const int qb  = (int)gridDim.x - 1 - (int)blockIdx.x;
    const int tid = threadIdx.x, lane = tid & 31, wid = tid >> 5;
    const int q0  = qb * 128;
    const int nkb = qb * 2 + 2;

    // Issue Q loads (hi+lo): 2048 16B chunks
#pragma unroll
    for (int i = 0; i < 8; i++) {
        int idx = tid + i * 256;
        int arr = idx >> 10, rem = idx & 1023;
        int row = rem >> 3, c16 = rem & 7;
        const __nv_bfloat16* src = (arr ? Qlo_g : Qhi_g)
            + (size_t)(q0 + row) * DIM + h * DHEAD + c16 * 8;
        cp16((arr ? qlb : qhb) + (uint32_t)(row * PADB + c16 * 16), src);
    }

    // K/V stage loader: 1536 chunks (Khi, Klo, Vh)
    auto load_kv = [&](int kb, int b) {
        const int j0 = kb * 64;
        const uint32_t sb = stg + (uint32_t)b * STAGEB;
#pragma unroll
        for (int i = 0; i < 6; i++) {
            int idx = tid + i * 256;
            int arr = idx >> 9, rem = idx & 511;
            int row = rem >> 3, c16 = rem & 7;
            size_t goff = (size_t)(j0 + row) * DIM + h * DHEAD + c16 * 8;
            const void* src = (arr == 0) ? (const void*)(Khi_g + goff)
                            : (arr == 1) ? (const void*)(Klo_g + goff)
                                         : (const void*)(Vh_g + goff);
            cp16(sb + (uint32_t)(arr * KTILEB + row * PADB + c16 * 16), src);
        }
        cp_commit();
    };

    load_kv(0, 0);
    cp_wait<0>();
    __syncthreads();

    // Hoist Q fragments
    uint32_t aHi[4][4], aLo[4][4];
    {
        const uint32_t aoff = (uint32_t)((wid * 16 + (lane & 15)) * PADB + (lane >> 4) * 16);
#pragma unroll
        for (int t = 0; t < 4; t++) {
            ldm_x4(aHi[t], qhb + aoff + t * 32);
            ldm_x4(aLo[t], qlb + aoff + t * 32);
        }
    }

    float o[8][4], lf[4];
#pragma unroll
    for (int g = 0; g < 8; g++)
#pragma unroll
        for (int r = 0; r < 4; r++) o[g][r] = 0.f;
#pragma unroll
    for (int r = 0; r < 4; r++) lf[r] = 0.f;
    float m0 = -1e30f, m1 = -1e30f;

    const int grp = lane >> 3;
    const uint32_t bRowOff = (uint32_t)(((grp >> 1) * 8 + (lane & 7)) * PADB + (grp & 1) * 16);
    const uint32_t vRowOff = (uint32_t)((((lane & 7) + 8 * (grp & 1))) * PADB + (lane >> 4) * 16);

    for (int kb = 0; kb < nkb; kb++) {
        const int b = kb & 1;
        if (kb + 1 < nkb) { load_kv(kb + 1, b ^ 1); cp_wait<1>(); }
        else              { cp_wait<0>(); }
        __syncthreads();

        const int j0 = kb * 64;
        if (q0 + wid * 16 + 15 >= j0) {       // warp not fully masked
            const uint32_t khb = stg + (uint32_t)b * STAGEB;
            const uint32_t klb = khb + KTILEB;
            const uint32_t vhb = klb + KTILEB;

            float s[8][4];
#pragma unroll
            for (int g = 0; g < 8; g++)
#pragma unroll
                for (int r = 0; r < 4; r++) s[g][r] = 0.f;

#pragma unroll
            for (int pass = 0; pass < 3; pass++) {
                const uint32_t bb = (pass == 1) ? klb : khb;
#pragma unroll
                for (int t = 0; t < 4; t++) {
                    const uint32_t* a = (pass < 2) ? aHi[t] : aLo[t];
#pragma unroll
                    for (int g = 0; g < 4; g++) {
                        uint32_t bq[4];
                        ldm_x4(bq, bb + (uint32_t)(g * 16 * PADB + t * 32) + bRowOff);
                        mma16816(s[g * 2],     a, &bq[0]);
                        mma16816(s[g * 2 + 1], a, &bq[2]);
                    }
                }
            }

            const int r0 = q0 + wid * 16 + (lane >> 2);
            const int r1 = r0 + 8;

            if (kb >= nkb - 2) {
                const int cb = j0 + (lane & 3) * 2;
#pragma unroll
                for (int g = 0; g < 8; g++) {
                    int c0 = cb + g * 8;
                    if (c0 > r0)     s[g][0] = -1e30f;
                    if (c0 + 1 > r0) s[g][1] = -1e30f;
                    if (c0 > r1)     s[g][2] = -1e30f;
                    if (c0 + 1 > r1) s[g][3] = -1e30f;
                }
            }

            float mx0 = -1e30f, mx1 = -1e30f;
#pragma unroll
            for (int g = 0; g < 8; g++) {
                mx0 = fmaxf(mx0, fmaxf(s[g][0], s[g][1]));
                mx1 = fmaxf(mx1, fmaxf(s[g][2], s[g][3]));
            }
            mx0 = fmaxf(mx0, __shfl_xor_sync(0xffffffffu, mx0, 1));
            mx0 = fmaxf(mx0, __shfl_xor_sync(0xffffffffu, mx0, 2));
            mx1 = fmaxf(mx1, __shfl_xor_sync(0xffffffffu, mx1, 1));
            mx1 = fmaxf(mx1, __shfl_xor_sync(0xffffffffu, mx1, 2));

            const float mn0 = fmaxf(m0, mx0), mn1 = fmaxf(m1, mx1);
            const float cs0 = ex2f(m0 - mn0), cs1 = ex2f(m1 - mn1);
            m0 = mn0; m1 = mn1;
#pragma unroll
            for (int g = 0; g < 8; g++) {
                o[g][0] *= cs0; o[g][1] *= cs0; o[g][2] *= cs1; o[g][3] *= cs1;
            }
            lf[0] *= cs0; lf[1] *= cs0; lf[2] *= cs1; lf[3] *= cs1;

            uint32_t pa[4][4];
#pragma unroll
            for (int g = 0; g < 8; g++) {
                uint32_t p01 = exp2_f16x2(s[g][0] - mn0, s[g][1] - mn0);
                uint32_t p23 = exp2_f16x2(s[g][2] - mn1, s[g][3] - mn1);
                if ((g & 1) == 0) { pa[g >> 1][0] = p01; pa[g >> 1][1] = p23; }
                else              { pa[g >> 1][2] = p01; pa[g >> 1][3] = p23; }
            }

            const uint32_t ONES = 0x3C003C00u;
#pragma unroll
            for (int t = 0; t < 4; t++) {
#pragma unroll
                for (int g = 0; g < 4; g++) {
                    uint32_t bv[4];
                    ldm_x4t(bv, vhb + (uint32_t)(t * 16 * PADB + g * 32) + vRowOff);
                    mma16816h(o[g * 2],     pa[t], bv[0], bv[1]);
                    mma16816h(o[g * 2 + 1], pa[t], bv[2], bv[3]);
                }
                mma16816h(lf, pa[t], ONES, ONES);
            }
        }
        __syncthreads();
    }

    // Epilogue: write split [hi|hi|lo] layout straight into OS
    const float inv0 = 1.f / lf[0], inv1 = 1.f / lf[2];
    const int r0 = q0 + wid * 16 + (lane >> 2);
    const int colb = h * DHEAD + (lane & 3) * 2;
#pragma unroll
    for (int g = 0; g < 8; g++) {
        int col = colb + g * 8;
        float a0 = o[g][0] * inv0, a1 = o[g][1] * inv0;
        float a2 = o[g][2] * inv1, a3 = o[g][3] * inv1;
        float h0 = __bfloat162float(__float2bfloat16(a0));
        float h1 = __bfloat162float(__float2bfloat16(a1));
        float h2 = __bfloat162float(__float2bfloat16(a2));
        float h3 = __bfloat162float(__float2bfloat16(a3));
        __nv_bfloat16* b0 = OS + (size_t)r0 * KP;
        __nv_bfloat16* b1 = OS + (size_t)(r0 + 8) * KP;
        store_bf16x2(b0 + col,            h0, h1);
        store_bf16x2(b0 + DIM + col,      h0, h1);
        store_bf16x2(b0 + 2 * DIM + col,  a0 - h0, a1 - h1);
        store_bf16x2(b1 + col,            h2, h3);
        store_bf16x2(b1 + DIM + col,      h2, h3);
        store_bf16x2(b1 + 2 * DIM + col,  a2 - h2, a3 - h3);
    }
}

// ---------------------------------------------------------------------------
extern "C" void kernel_launch(void* const* d_in, const int* in_sizes, int n_in,
                              void* d_out, int out_size)
{
    const float* x  = (const float*)d_in[0];
    const float* Wq = (const float*)d_in[1];
    const float* Wk = (const float*)d_in[2];
    const float* Wv = (const float*)d_in[3];
    const float* Wo = (const float*)d_in[4];
    const float* bo = (const float*)d_in[5];
    float* out = (float*)d_out;

    __nv_bfloat16 *XS, *WTq, *WTk, *WTv, *WTo, *OS;
    __nv_bfloat16 *Qhi, *Qlo, *Khi, *Klo;
    __half *Vh;
    cudaGetSymbolAddress((void**)&XS, g_XS);
    cudaGetSymbolAddress((void**)&WTq, g_WTq);
    cudaGetSymbolAddress((void**)&WTk, g_WTk);
    cudaGetSymbolAddress((void**)&WTv, g_WTv);
    cudaGetSymbolAddress((void**)&WTo, g_WTo);
    cudaGetSymbolAddress((void**)&OS, g_OS);
    cudaGetSymbolAddress((void**)&Qhi, g_Qhi);
    cudaGetSymbolAddress((void**)&Qlo, g_Qlo);
    cudaGetSymbolAddress((void**)&Khi, g_Khi);
    cudaGetSymbolAddress((void**)&Klo, g_Klo);
    cudaGetSymbolAddress((void**)&Vh, g_Vh);

    cudaFuncSetAttribute(attn_mma_kernel,
                         cudaFuncAttributeMaxDynamicSharedMemorySize, ATT_SMEM);

    dim3 wgrid(DIM / 32, DIM / 32);
    split_w_kernel<<<wgrid, 256>>>(Wq, WTq, DIM, DIM);
    split_w_kernel<<<wgrid, 256>>>(Wk, WTk, DIM, DIM);
    split_w_kernel<<<wgrid, 256>>>(Wv, WTv, DIM, DIM);
    split_w_kernel<<<wgrid, 256>>>(Wo, WTo, DIM, DIM);

    split_a_kernel<<<(SEQ * DIM) / (256 * 4), 256>>>(x, XS, DIM);

    dim3 ggrid(DIM / 128, SEQ / 128);
    gemm_mma_kernel<0><<<ggrid, 256>>>(XS, WTq, nullptr, nullptr, Qhi, Qlo, nullptr, DIM);
    gemm_mma_kernel<1><<<ggrid, 256>>>(XS, WTk, nullptr, nullptr, Khi, Klo, nullptr, DIM);
    gemm_mma_kernel<2><<<ggrid, 256>>>(XS, WTv, nullptr, nullptr, nullptr, nullptr, Vh, DIM);

    dim3 agrid(SEQ / 128, HEADS);
    attn_mma_kernel<<<agrid, 256, ATT_SMEM>>>(Qhi, Qlo, Khi, Klo, Vh, OS);

    gemm_mma_kernel<3><<<ggrid, 256>>>(OS, WTo, bo, out, nullptr, nullptr, nullptr, DIM);
}

// round 13
// speedup vs baseline: 4.8099x; 1.2183x over previous
#include <cuda_runtime.h>
#include <cuda_bf16.h>
#include <cuda_fp16.h>
#include <math.h>
#include <stdint.h>

#define SEQ    4096
#define DIM    1024
#define HEADS  16
#define DHEAD  64
#define KP     (3 * DIM)          // split-K': [hi|hi|lo] / [hi|lo|hi]
#define BK     32
#define SCLOG2 0.1803368801111204f   // (1/8) * log2(e)

// ---------------- scratch (__device__ globals; no allocs allowed) ----------
__device__ __nv_bfloat16 g_XS[SEQ * KP];
__device__ __nv_bfloat16 g_WTq[DIM * KP];
__device__ __nv_bfloat16 g_WTk[DIM * KP];
__device__ __nv_bfloat16 g_WTv[DIM * KP];
__device__ __nv_bfloat16 g_WTo[DIM * KP];
__device__ __half        g_Qh [SEQ * DIM];   // fp16, pre-scaled by SCLOG2
__device__ __half        g_Khi[SEQ * DIM];   // fp16 hi
__device__ __half        g_Klo[SEQ * DIM];   // fp16 lo
__device__ __half        g_Vh [SEQ * DIM];
__device__ __nv_bfloat16 g_OS[SEQ * KP];     // attention out, split layout

// ---------------- helpers (non-arch-specific PTX, sm_80+) ------------------
__device__ __forceinline__ uint32_t smem_u32(const void* p) {
    return (uint32_t)__cvta_generic_to_shared(p);
}
__device__ __forceinline__ void cp16(uint32_t dst, const void* src) {
    asm volatile("cp.async.cg.shared.global [%0], [%1], 16;"
                 :: "r"(dst), "l"(src) : "memory");
}
__device__ __forceinline__ void cp_commit() {
    asm volatile("cp.async.commit_group;" ::: "memory");
}
template <int N>
__device__ __forceinline__ void cp_wait() {
    asm volatile("cp.async.wait_group %0;" :: "n"(N) : "memory");
}
__device__ __forceinline__ void ldm_x4(uint32_t* r, uint32_t addr) {
    asm volatile("ldmatrix.sync.aligned.m8n8.x4.shared.b16 {%0,%1,%2,%3}, [%4];"
                 : "=r"(r[0]), "=r"(r[1]), "=r"(r[2]), "=r"(r[3]) : "r"(addr));
}
__device__ __forceinline__ void ldm_x4t(uint32_t* r, uint32_t addr) {
    asm volatile("ldmatrix.sync.aligned.m8n8.x4.trans.shared.b16 {%0,%1,%2,%3}, [%4];"
                 : "=r"(r[0]), "=r"(r[1]), "=r"(r[2]), "=r"(r[3]) : "r"(addr));
}
__device__ __forceinline__ void mma16816(float* c, const uint32_t* a,
                                         const uint32_t* b) {
    asm volatile("mma.sync.aligned.m16n8k16.row.col.f32.bf16.bf16.f32 "
                 "{%0,%1,%2,%3}, {%4,%5,%6,%7}, {%8,%9}, {%0,%1,%2,%3};"
                 : "+f"(c[0]), "+f"(c[1]), "+f"(c[2]), "+f"(c[3])
                 : "r"(a[0]), "r"(a[1]), "r"(a[2]), "r"(a[3]),
                   "r"(b[0]), "r"(b[1]));
}
__device__ __forceinline__ void mma16816h(float* c, const uint32_t* a,
                                          uint32_t b0, uint32_t b1) {
    asm volatile("mma.sync.aligned.m16n8k16.row.col.f32.f16.f16.f32 "
                 "{%0,%1,%2,%3}, {%4,%5,%6,%7}, {%8,%9}, {%0,%1,%2,%3};"
                 : "+f"(c[0]), "+f"(c[1]), "+f"(c[2]), "+f"(c[3])
                 : "r"(a[0]), "r"(a[1]), "r"(a[2]), "r"(a[3]),
                   "r"(b0), "r"(b1));
}
__device__ __forceinline__ uint32_t exp2_f16x2(float lo, float hi) {
    uint32_t hreg, p;
    asm volatile("cvt.rn.f16x2.f32 %0, %1, %2;" : "=r"(hreg) : "f"(hi), "f"(lo));
    asm volatile("ex2.approx.f16x2 %0, %1;" : "=r"(p) : "r"(hreg));
    return p;
}
__device__ __forceinline__ float ex2f(float x) {
    float y; asm volatile("ex2.approx.f32 %0, %1;" : "=f"(y) : "f"(x)); return y;
}
__device__ __forceinline__ void store_bf16x2(__nv_bfloat16* p, float a, float b) {
    __nv_bfloat162 v(__float2bfloat16(a), __float2bfloat16(b));
    *(__nv_bfloat162*)p = v;
}

// ---------------------------------------------------------------------------
// Split conversions (GEMM inputs)
// ---------------------------------------------------------------------------
__global__ void __launch_bounds__(256)
split_a_kernel(const float* __restrict__ X, __nv_bfloat16* __restrict__ XS, int K)
{
    int idx = (blockIdx.x * 256 + threadIdx.x) * 4;
    int m = idx / K, k = idx % K;
    float4 v = *(const float4*)(X + idx);
    __nv_bfloat16 h0 = __float2bfloat16(v.x), h1 = __float2bfloat16(v.y);
    __nv_bfloat16 h2 = __float2bfloat16(v.z), h3 = __float2bfloat16(v.w);
    __nv_bfloat16 l0 = __float2bfloat16(v.x - __bfloat162float(h0));
    __nv_bfloat16 l1 = __float2bfloat16(v.y - __bfloat162float(h1));
    __nv_bfloat16 l2 = __float2bfloat16(v.z - __bfloat162float(h2));
    __nv_bfloat16 l3 = __float2bfloat16(v.w - __bfloat162float(h3));
    __nv_bfloat162 hA = __nv_bfloat162(h0, h1), hB = __nv_bfloat162(h2, h3);
    __nv_bfloat162 lA = __nv_bfloat162(l0, l1), lB = __nv_bfloat162(l2, l3);
    __nv_bfloat162* base = (__nv_bfloat162*)(XS + (size_t)m * (3 * K) + k);
    base[0] = hA; base[1] = hB;
    base[K / 2] = hA; base[K / 2 + 1] = hB;
    base[K] = lA; base[K + 1] = lB;
}

__global__ void __launch_bounds__(256)
split_w_kernel(const float* __restrict__ W, __nv_bfloat16* __restrict__ WT, int K, int N)
{
    __shared__ float t[32][33];
    const int tx = threadIdx.x & 31, ty = threadIdx.x >> 5;
    const int k0 = blockIdx.y * 32, n0 = blockIdx.x * 32;
#pragma unroll
    for (int i = 0; i < 4; i++)
        t[ty + i * 8][tx] = W[(size_t)(k0 + ty + i * 8) * N + n0 + tx];
    __syncthreads();
#pragma unroll
    for (int i = 0; i < 4; i++) {
        float v = t[tx][ty + i * 8];
        __nv_bfloat16 h = __float2bfloat16(v);
        __nv_bfloat16 l = __float2bfloat16(v - __bfloat162float(h));
        int n = n0 + ty + i * 8;
        __nv_bfloat16* row = WT + (size_t)n * (3 * K);
        row[k0 + tx] = h;
        row[K + k0 + tx] = l;
        row[2 * K + k0 + tx] = h;
    }
}

// ---------------------------------------------------------------------------
// HMMA GEMM (TN). MODE: 0 = Q (scale, fp16 single, 2-pass K'=2048),
// 1 = K (fp16 hi/lo, 2-pass), 2 = V (fp16, 3-pass), 3 = fp32 + bias (3-pass).
// ---------------------------------------------------------------------------
#define ROWB   80
#define TILEB  (128 * ROWB)

template <int MODE>
__global__ void __launch_bounds__(256, 2)
gemm_mma_kernel(const __nv_bfloat16* __restrict__ A,
                const __nv_bfloat16* __restrict__ Bt,
                const float* __restrict__ bias, float* __restrict__ C,
                __half* __restrict__ H0, __half* __restrict__ H1, int N)
{
    __shared__ __align__(128) char smem[4 * TILEB];
    const int NITER = (MODE <= 1) ? 64 : 96;   // 2-pass vs 3-pass K'

    const int tid  = threadIdx.x;
    const int lane = tid & 31, wid = tid >> 5;
    const int wm0  = (wid & 1) * 64;
    const int wn0  = (wid >> 1) * 32;
    const int m0 = blockIdx.y * 128, n0 = blockIdx.x * 128;

    const uint32_t sbase = smem_u32(smem);
    const uint32_t sA[2] = { sbase,             sbase + TILEB };
    const uint32_t sB[2] = { sbase + 2 * TILEB, sbase + 3 * TILEB };

    float acc[4][4][4];
#pragma unroll
    for (int i = 0; i < 4; i++)
#pragma unroll
        for (int j = 0; j < 4; j++)
#pragma unroll
            for (int r = 0; r < 4; r++) acc[i][j][r] = 0.f;

    const int lrow = tid >> 2, lc16 = tid & 3;
    auto load_tile = [&](int c, int b) {
        const int kc0 = c * BK;
#pragma unroll
        for (int i = 0; i < 2; i++) {
            int row = lrow + i * 64;
            uint32_t so = (uint32_t)(row * ROWB + lc16 * 16);
            cp16(sA[b] + so, A  + (size_t)(m0 + row) * KP + kc0 + lc16 * 8);
            cp16(sB[b] + so, Bt + (size_t)(n0 + row) * KP + kc0 + lc16 * 8);
        }
        cp_commit();
    };

    load_tile(0, 0);

    for (int c = 0; c < NITER; c++) {
        const int b = c & 1;
        if (c + 1 < NITER) { load_tile(c + 1, b ^ 1); cp_wait<1>(); }
        else               { cp_wait<0>(); }
        __syncthreads();

#pragma unroll
        for (int s = 0; s < 2; s++) {
            uint32_t af[4][4], bf[2][4];
#pragma unroll
            for (int i = 0; i < 4; i++) {
                uint32_t addr = sA[b] + (uint32_t)((wm0 + i * 16 + (lane & 15)) * ROWB
                               + s * 32 + (lane >> 4) * 16);
                ldm_x4(af[i], addr);
            }
#pragma unroll
            for (int j = 0; j < 2; j++) {
                int grp = lane >> 3;
                int row = wn0 + j * 16 + (grp >> 1) * 8 + (lane & 7);
                uint32_t addr = sB[b] + (uint32_t)(row * ROWB + s * 32 + (grp & 1) * 16);
                ldm_x4(bf[j], addr);
            }
#pragma unroll
            for (int i = 0; i < 4; i++)
#pragma unroll
                for (int jj = 0; jj < 4; jj++)
                    mma16816(acc[i][jj], af[i], &bf[jj >> 1][(jj & 1) * 2]);
        }
        __syncthreads();
    }

#pragma unroll
    for (int i = 0; i < 4; i++) {
        int row = m0 + wm0 + i * 16 + (lane >> 2);
#pragma unroll
        for (int jj = 0; jj < 4; jj++) {
            int col = n0 + wn0 + jj * 8 + (lane & 3) * 2;
            float v[4] = { acc[i][jj][0], acc[i][jj][1],
                           acc[i][jj][2], acc[i][jj][3] };
            if (MODE == 3) {
                float b0 = bias[col], b1 = bias[col + 1];
                *(float2*)&C[(size_t)row * N + col] =
                    make_float2(v[0] + b0, v[1] + b1);
                *(float2*)&C[(size_t)(row + 8) * N + col] =
                    make_float2(v[2] + b0, v[3] + b1);
            } else if (MODE == 0) {
                *(__half2*)&H0[(size_t)row * N + col] =
                    __floats2half2_rn(v[0] * SCLOG2, v[1] * SCLOG2);
                *(__half2*)&H0[(size_t)(row + 8) * N + col] =
                    __floats2half2_rn(v[2] * SCLOG2, v[3] * SCLOG2);
            } else if (MODE == 2) {
                *(__half2*)&H0[(size_t)row * N + col] =
                    __floats2half2_rn(v[0], v[1]);
                *(__half2*)&H0[(size_t)(row + 8) * N + col] =
                    __floats2half2_rn(v[2], v[3]);
            } else {            // MODE 1: fp16 hi/lo split
                float h_[4], l_[4];
#pragma unroll
                for (int r = 0; r < 4; r++) {
                    h_[r] = __half2float(__float2half(v[r]));
                    l_[r] = v[r] - h_[r];
                }
                *(__half2*)&H0[(size_t)row * N + col]       = __floats2half2_rn(h_[0], h_[1]);
                *(__half2*)&H0[(size_t)(row + 8) * N + col] = __floats2half2_rn(h_[2], h_[3]);
                *(__half2*)&H1[(size_t)row * N + col]       = __floats2half2_rn(l_[0], l_[1]);
                *(__half2*)&H1[(size_t)(row + 8) * N + col] = __floats2half2_rn(l_[2], l_[3]);
            }
        }
    }
}

// ---------------------------------------------------------------------------
// HMMA flash attention (causal). Q fp16 (pre-scaled), K fp16 hi/lo, V fp16.
// S = Q.Khi + Q.Klo (2 passes). cp.async double-buffered K/V stages.
// Output written in split [hi|hi|lo] bf16 layout.
// ---------------------------------------------------------------------------
#define PADK     72
#define PADB     144
#define QBYTES   (128 * PADB)                 // 18432
#define KTILEB   (64 * PADB)                  // 9216
#define STAGEB   (3 * KTILEB)                 // 27648
#define ATT_SMEM (QBYTES + 2 * STAGEB)        // 73728

__global__ void __launch_bounds__(256)
attn_mma_kernel(const __half* __restrict__ Qh_g,
                const __half* __restrict__ Khi_g,
                const __half* __restrict__ Klo_g,
                const __half* __restrict__ Vh_g,
                __nv_bfloat16* __restrict__ OS)
{
    extern __shared__ __align__(16) char sraw[];
    const uint32_t sbase = smem_u32(sraw);
    const uint32_t qhb = sbase;
    const uint32_t stg = sbase + QBYTES;

    const int h   = blockIdx.y;
    const int qb  = (int)gridDim.x - 1 - (int)blockIdx.x;
    const int tid = threadIdx.x, lane = tid & 31, wid = tid >> 5;
    const int q0  = qb * 128;
    const int nkb = qb * 2 + 2;

    // Issue Q loads: 1024 16B chunks
#pragma unroll
    for (int i = 0; i < 4; i++) {
        int idx = tid + i * 256;
        int row = idx >> 3, c16 = idx & 7;
        cp16(qhb + (uint32_t)(row * PADB + c16 * 16),
             Qh_g + (size_t)(q0 + row) * DIM + h * DHEAD + c16 * 8);
    }

    // K/V stage loader: 1536 chunks (Khi, Klo, Vh)
    auto load_kv = [&](int kb, int b) {
        const int j0 = kb * 64;
        const uint32_t sb = stg + (uint32_t)b * STAGEB;
#pragma unroll
        for (int i = 0; i < 6; i++) {
            int idx = tid + i * 256;
            int arr = idx >> 9, rem = idx & 511;
            int row = rem >> 3, c16 = rem & 7;
            size_t goff = (size_t)(j0 + row) * DIM + h * DHEAD + c16 * 8;
            const void* src = (arr == 0) ? (const void*)(Khi_g + goff)
                            : (arr == 1) ? (const void*)(Klo_g + goff)
                                         : (const void*)(Vh_g + goff);
            cp16(sb + (uint32_t)(arr * KTILEB + row * PADB + c16 * 16), src);
        }
        cp_commit();
    };

    load_kv(0, 0);
    cp_wait<0>();
    __syncthreads();

    // Hoist Q fragments
    uint32_t aH[4][4];
    {
        const uint32_t aoff = (uint32_t)((wid * 16 + (lane & 15)) * PADB + (lane >> 4) * 16);
#pragma unroll
        for (int t = 0; t < 4; t++)
            ldm_x4(aH[t], qhb + aoff + t * 32);
    }

    float o[8][4], lf[4];
#pragma unroll
    for (int g = 0; g < 8; g++)
#pragma unroll
        for (int r = 0; r < 4; r++) o[g][r] = 0.f;
#pragma unroll
    for (int r = 0; r < 4; r++) lf[r] = 0.f;
    float m0 = -1e30f, m1 = -1e30f;

    const int grp = lane >> 3;
    const uint32_t bRowOff = (uint32_t)(((grp >> 1) * 8 + (lane & 7)) * PADB + (grp & 1) * 16);
    const uint32_t vRowOff = (uint32_t)((((lane & 7) + 8 * (grp & 1))) * PADB + (lane >> 4) * 16);

    for (int kb = 0; kb < nkb; kb++) {
        const int b = kb & 1;
        if (kb + 1 < nkb) { load_kv(kb + 1, b ^ 1); cp_wait<1>(); }
        else              { cp_wait<0>(); }
        __syncthreads();

        const int j0 = kb * 64;
        if (q0 + wid * 16 + 15 >= j0) {
            const uint32_t khb = stg + (uint32_t)b * STAGEB;
            const uint32_t klb = khb + KTILEB;
            const uint32_t vhb = klb + KTILEB;

            float s[8][4];
#pragma unroll
            for (int g = 0; g < 8; g++)
#pragma unroll
                for (int r = 0; r < 4; r++) s[g][r] = 0.f;

            // S = Q.Khi + Q.Klo (fp16, 2 passes)
#pragma unroll
            for (int pass = 0; pass < 2; pass++) {
                const uint32_t bb = pass ? klb : khb;
#pragma unroll
                for (int t = 0; t < 4; t++) {
#pragma unroll
                    for (int g = 0; g < 4; g++) {
                        uint32_t bq[4];
                        ldm_x4(bq, bb + (uint32_t)(g * 16 * PADB + t * 32) + bRowOff);
                        mma16816h(s[g * 2],     aH[t], bq[0], bq[1]);
                        mma16816h(s[g * 2 + 1], aH[t], bq[2], bq[3]);
                    }
                }
            }

            const int r0 = q0 + wid * 16 + (lane >> 2);
            const int r1 = r0 + 8;

            if (kb >= nkb - 2) {
                const int cb = j0 + (lane & 3) * 2;
#pragma unroll
                for (int g = 0; g < 8; g++) {
                    int c0 = cb + g * 8;
                    if (c0 > r0)     s[g][0] = -1e30f;
                    if (c0 + 1 > r0) s[g][1] = -1e30f;
                    if (c0 > r1)     s[g][2] = -1e30f;
                    if (c0 + 1 > r1) s[g][3] = -1e30f;
                }
            }

            float mx0 = -1e30f, mx1 = -1e30f;
#pragma unroll
            for (int g = 0; g < 8; g++) {
                mx0 = fmaxf(mx0, fmaxf(s[g][0], s[g][1]));
                mx1 = fmaxf(mx1, fmaxf(s[g][2], s[g][3]));
            }
            mx0 = fmaxf(mx0, __shfl_xor_sync(0xffffffffu, mx0, 1));
            mx0 = fmaxf(mx0, __shfl_xor_sync(0xffffffffu, mx0, 2));
            mx1 = fmaxf(mx1, __shfl_xor_sync(0xffffffffu, mx1, 1));
            mx1 = fmaxf(mx1, __shfl_xor_sync(0xffffffffu, mx1, 2));

            const float mn0 = fmaxf(m0, mx0), mn1 = fmaxf(m1, mx1);
            const float cs0 = ex2f(m0 - mn0), cs1 = ex2f(m1 - mn1);
            m0 = mn0; m1 = mn1;
#pragma unroll
            for (int g = 0; g < 8; g++) {
                o[g][0] *= cs0; o[g][1] *= cs0; o[g][2] *= cs1; o[g][3] *= cs1;
            }
            lf[0] *= cs0; lf[1] *= cs0; lf[2] *= cs1; lf[3] *= cs1;

            uint32_t pa[4][4];
#pragma unroll
            for (int g = 0; g < 8; g++) {
                uint32_t p01 = exp2_f16x2(s[g][0] - mn0, s[g][1] - mn0);
                uint32_t p23 = exp2_f16x2(s[g][2] - mn1, s[g][3] - mn1);
                if ((g & 1) == 0) { pa[g >> 1][0] = p01; pa[g >> 1][1] = p23; }
                else              { pa[g >> 1][2] = p01; pa[g >> 1][3] = p23; }
            }

            const uint32_t ONES = 0x3C003C00u;
#pragma unroll
            for (int t = 0; t < 4; t++) {
#pragma unroll
                for (int g = 0; g < 4; g++) {
                    uint32_t bv[4];
                    ldm_x4t(bv, vhb + (uint32_t)(t * 16 * PADB + g * 32) + vRowOff);
                    mma16816h(o[g * 2],     pa[t], bv[0], bv[1]);
                    mma16816h(o[g * 2 + 1], pa[t], bv[2], bv[3]);
                }
                mma16816h(lf, pa[t], ONES, ONES);
            }
        }
        __syncthreads();
    }

    // Epilogue: write split [hi|hi|lo] bf16 layout straight into OS
    const float inv0 = 1.f / lf[0], inv1 = 1.f / lf[2];
    const int r0 = q0 + wid * 16 + (lane >> 2);
    const int colb = h * DHEAD + (lane & 3) * 2;
#pragma unroll
    for (int g = 0; g < 8; g++) {
        int col = colb + g * 8;
        float a0 = o[g][0] * inv0, a1 = o[g][1] * inv0;
        float a2 = o[g][2] * inv1, a3 = o[g][3] * inv1;
        float h0 = __bfloat162float(__float2bfloat16(a0));
        float h1 = __bfloat162float(__float2bfloat16(a1));
        float h2 = __bfloat162float(__float2bfloat16(a2));
        float h3 = __bfloat162float(__float2bfloat16(a3));
        __nv_bfloat16* b0 = OS + (size_t)r0 * KP;
        __nv_bfloat16* b1 = OS + (size_t)(r0 + 8) * KP;
        store_bf16x2(b0 + col,            h0, h1);
        store_bf16x2(b0 + DIM + col,      h0, h1);
        store_bf16x2(b0 + 2 * DIM + col,  a0 - h0, a1 - h1);
        store_bf16x2(b1 + col,            h2, h3);
        store_bf16x2(b1 + DIM + col,      h2, h3);
        store_bf16x2(b1 + 2 * DIM + col,  a2 - h2, a3 - h3);
    }
}

// ---------------------------------------------------------------------------
extern "C" void kernel_launch(void* const* d_in, const int* in_sizes, int n_in,
                              void* d_out, int out_size)
{
    const float* x  = (const float*)d_in[0];
    const float* Wq = (const float*)d_in[1];
    const float* Wk = (const float*)d_in[2];
    const float* Wv = (const float*)d_in[3];
    const float* Wo = (const float*)d_in[4];
    const float* bo = (const float*)d_in[5];
    float* out = (float*)d_out;

    __nv_bfloat16 *XS, *WTq, *WTk, *WTv, *WTo, *OS;
    __half *Qh, *Khi, *Klo, *Vh;
    cudaGetSymbolAddress((void**)&XS, g_XS);
    cudaGetSymbolAddress((void**)&WTq, g_WTq);
    cudaGetSymbolAddress((void**)&WTk, g_WTk);
    cudaGetSymbolAddress((void**)&WTv, g_WTv);
    cudaGetSymbolAddress((void**)&WTo, g_WTo);
    cudaGetSymbolAddress((void**)&OS, g_OS);
    cudaGetSymbolAddress((void**)&Qh, g_Qh);
    cudaGetSymbolAddress((void**)&Khi, g_Khi);
    cudaGetSymbolAddress((void**)&Klo, g_Klo);
    cudaGetSymbolAddress((void**)&Vh, g_Vh);

    cudaFuncSetAttribute(attn_mma_kernel,
                         cudaFuncAttributeMaxDynamicSharedMemorySize, ATT_SMEM);

    dim3 wgrid(DIM / 32, DIM / 32);
    split_w_kernel<<<wgrid, 256>>>(Wq, WTq, DIM, DIM);
    split_w_kernel<<<wgrid, 256>>>(Wk, WTk, DIM, DIM);
    split_w_kernel<<<wgrid, 256>>>(Wv, WTv, DIM, DIM);
    split_w_kernel<<<wgrid, 256>>>(Wo, WTo, DIM, DIM);

    split_a_kernel<<<(SEQ * DIM) / (256 * 4), 256>>>(x, XS, DIM);

    dim3 ggrid(DIM / 128, SEQ / 128);
    gemm_mma_kernel<0><<<ggrid, 256>>>(XS, WTq, nullptr, nullptr, Qh, nullptr, DIM);
    gemm_mma_kernel<1><<<ggrid, 256>>>(XS, WTk, nullptr, nullptr, Khi, Klo, DIM);
    gemm_mma_kernel<2><<<ggrid, 256>>>(XS, WTv, nullptr, nullptr, Vh, nullptr, DIM);

    dim3 agrid(SEQ / 128, HEADS);
    attn_mma_kernel<<<agrid, 256, ATT_SMEM>>>(Qh, Khi, Klo, Vh, OS);

    gemm_mma_kernel<3><<<ggrid, 256>>>(OS, WTo, bo, out, nullptr, nullptr, DIM);
}